// round 17
// baseline (speedup 1.0000x reference)
#include <cuda_runtime.h>
#include <cuda_bf16.h>
#include <cstdint>

constexpr int TIMESTEPS = 1000;
constexpr int B = 4;
constexpr int N = 2048;                                // power of two
constexpr long long E = (long long)N * (N - 1) / 2;    // 2,096,128
constexpr int EI = (int)E;
constexpr int NPAIR = B * (N / 2);                     // 4096 work pairs
constexpr int GRID = 296;                              // 148 SMs x 2 CTAs
constexpr int NTHR = 512;
constexpr int NBUF = 4;                                // depth-3 prefetch

// Per-buffer SMEM word layout: adj[2056] | u[2056] | q[2064] = 6176 words
constexpr int W_U   = 2056;
constexpr int W_Q   = 4112;
constexpr int BUFW  = 6176;
constexpr int BUFB  = BUFW * 4;                        // 24704 B, 16B-aligned
constexpr int SMEM_DYN = NBUF * BUFB;                  // 98816 B

// Cross-block reduction scratch. g_count self-resets (atomicInc wrap) -> graph-replay safe.
__device__ float        g_partials[GRID];
__device__ unsigned int g_count = 0;

struct Consts { float flip_t, omt, qt00, qt01, qt10, qt11; };

__device__ __forceinline__ float ex2(float x) {
    float r; asm("ex2.approx.f32 %0, %1;" : "=f"(r) : "f"(x)); return r;
}
__device__ __forceinline__ float rcp(float x) {
    float r; asm("rcp.approx.f32 %0, %1;" : "=f"(r) : "f"(x)); return r;
}

// TMA bulk copy: global -> shared::cta, completion counted on an mbarrier.
__device__ __forceinline__ void bulk(uint32_t dst, const void* src, uint32_t bytes,
                                     uint32_t mbar) {
    asm volatile("cp.async.bulk.shared::cta.global.mbarrier::complete_tx::bytes "
                 "[%0], [%1], %2, [%3];"
                 :: "r"(dst), "l"(src), "r"(bytes), "r"(mbar) : "memory");
}
__device__ __forceinline__ void mbar_init(uint32_t mbar, uint32_t cnt) {
    asm volatile("mbarrier.init.shared.b64 [%0], %1;" :: "r"(mbar), "r"(cnt) : "memory");
}
__device__ __forceinline__ void mbar_expect(uint32_t mbar, uint32_t bytes) {
    asm volatile("mbarrier.arrive.expect_tx.shared.b64 _, [%0], %1;"
                 :: "r"(mbar), "r"(bytes) : "memory");
}
__device__ __forceinline__ void mbar_wait(uint32_t mbar, uint32_t parity) {
    asm volatile(
        "{\n\t.reg .pred P;\n\t"
        "W_%=:\n\t"
        "mbarrier.try_wait.parity.acquire.cta.shared::cta.b64 P, [%0], %1, 0x989680;\n\t"
        "@P bra D_%=;\n\t"
        "bra W_%=;\n\t"
        "D_%=:\n\t}"
        :: "r"(mbar), "r"(parity) : "memory");
}

// Per-element loss term: qt via 4-entry LUT on (a!=0, x1); MUFU softplus.
__device__ __forceinline__ float term(int a, float uu, float x, const Consts& c) {
    bool  ab = (a != 0);
    float pa = ab ? c.omt : c.flip_t;          // Qt[t][a, 1]
    bool  x1 = uu < pa;                        // sampled bit
    float q0 = ab ? c.qt10 : c.qt00;
    float q1 = ab ? c.qt11 : c.qt01;
    float qt = x1 ? q1 : q0;
    float sp = __logf(1.0f + __expf(-fabsf(x)));   // log1p(exp(-|x|))
    return fmaf(-x, qt, fmaxf(x, 0.0f) + sp);
}

__device__ __forceinline__ float term4(int4 A, float4 U, const float* qp, const Consts& c) {
    float t0 = term(A.x, U.x, qp[0], c), t1 = term(A.y, U.y, qp[1], c);
    float t2 = term(A.z, U.z, qp[2], c), t3 = term(A.w, U.w, qp[3], c);
    return (t0 + t1) + (t2 + t3);
}

// Pair geometry: pair pid = (b, k) covers rows i=k (iA<=1023) and i=N-1-k
// (iB in [1024, 2047]); iA+iB = 2047 elements, (iA>>2)+(iB>>2) <= 511 groups.
struct Geom {
    int iA, iB, rowbaseA, rowbaseB, cA, cB, cA4;
    int galA, ofsA, galB, ofsB, cqA, cqB, cqA4;
    int b;
};
__device__ __forceinline__ Geom mk_geom(int pid) {
    Geom g;
    g.b  = pid >> 10;
    int k = pid & 1023;
    g.iA = k;  g.iB = N - 1 - k;
    g.rowbaseA = ((g.b << 11) + g.iA) << 11;
    g.rowbaseB = ((g.b << 11) + g.iB) << 11;
    int qrowA = g.b * EI + ((g.iA * (g.iA - 1)) >> 1);
    int qrowB = g.b * EI + ((g.iB * (g.iB - 1)) >> 1);
    g.cA  = (g.iA + 3) >> 2;  g.cB = (g.iB + 3) >> 2;  g.cA4 = g.cA << 2;
    g.galA = qrowA & ~3;  g.ofsA = qrowA & 3;
    g.galB = qrowB & ~3;  g.ofsB = qrowB & 3;
    g.cqA = g.iA ? ((g.iA + g.ofsA + 3) >> 2) : 0;
    g.cqB = (g.iB + g.ofsB + 3) >> 2;
    g.cqA4 = g.cqA << 2;
    return g;
}

// Single-thread TMA staging of one pair into the buffer at shared-addr s0.
// adj/u segments stay inside their 8KB rows; q's 16B rounding can over-read
// <=12B past the q buffer only on the last rows (stays in the mapped
// allocation; those smem slots are never consumed).
__device__ __forceinline__ void produce(const Geom& g,
                                        const int* __restrict__ adj,
                                        const float* __restrict__ u,
                                        const float* __restrict__ q,
                                        uint32_t s0, uint32_t mbar) {
    const uint32_t bytes = (uint32_t)(2 * (g.cA + g.cB) + g.cqA + g.cqB) * 16u;
    mbar_expect(mbar, bytes);
    const uint32_t sa = s0, su = s0 + W_U * 4, sq = s0 + W_Q * 4;
    if (g.cA) {
        bulk(sa, adj + g.rowbaseA, g.cA * 16u, mbar);
        bulk(su, u   + g.rowbaseA, g.cA * 16u, mbar);
        bulk(sq, q   + g.galA,     g.cqA * 16u, mbar);
    }
    bulk(sa + g.cA4 * 4,  adj + g.rowbaseB, g.cB * 16u, mbar);
    bulk(su + g.cA4 * 4,  u   + g.rowbaseB, g.cB * 16u, mbar);
    bulk(sq + g.cqA4 * 4, q   + g.galB,     g.cqB * 16u, mbar);
}

// Compute one staged pair: 512 threads, <=1 four-element group per thread
// (perfectly balanced; nfB+nfA <= 511), plus <=3-thread tails per row.
__device__ __forceinline__ float compute_pair(const Geom& g, const char* sbuf,
                                              const float* cc, int tid) {
    Consts c;
    {
        float4 c0 = reinterpret_cast<const float4*>(cc)[0];
        float4 c1 = reinterpret_cast<const float4*>(cc)[1];
        c.flip_t = c0.x; c.omt = c0.y; c.qt00 = c0.z; c.qt01 = c0.w;
        c.qt10 = c1.x; c.qt11 = c1.y;
    }
    const int*   s_adj = (const int*)sbuf;
    const float* s_u   = (const float*)(sbuf + W_U * 4);
    const float* s_q   = (const float*)(sbuf + W_Q * 4);

    const int nfB = g.iB >> 2, nfA = g.iA >> 2;

    float s = 0.0f;
    if (tid < nfB) {                 // row B group tid
        const int4*   a4 = reinterpret_cast<const int4*>(s_adj + g.cA4);
        const float4* u4 = reinterpret_cast<const float4*>(s_u + g.cA4);
        const float*  qB = s_q + g.cqA4 + g.ofsB;
        s = term4(a4[tid], u4[tid], qB + (tid << 2), c);
    } else if (tid - nfB < nfA) {    // row A group tid-nfB
        const int ga = tid - nfB;
        const int4*   a4 = reinterpret_cast<const int4*>(s_adj);
        const float4* u4 = reinterpret_cast<const float4*>(s_u);
        const float*  qA = s_q + g.ofsA;
        s = term4(a4[ga], u4[ga], qA + (ga << 2), c);
    }
    // tails (<=3 threads each)
    if (tid < (g.iB & 3)) {
        int e = (nfB << 2) + tid;
        s += term(s_adj[g.cA4 + e], s_u[g.cA4 + e], (s_q + g.cqA4 + g.ofsB)[e], c);
    }
    if (tid < (g.iA & 3)) {
        int e = (nfA << 2) + tid;
        s += term(s_adj[e], s_u[e], (s_q + g.ofsA)[e], c);
    }
    return s;
}

// Persistent CTAs (148x2, 512 threads), quad-buffered TMA pipeline: pairs
// j..j+3 cycle through 4 slots, so 3 pair-fetches are in flight while one is
// computed — the TMA/DRAM queue never drains between pairs.
__global__ __launch_bounds__(NTHR, 2)
void loss_kernel(const int* __restrict__ adj, const int* __restrict__ t,
                 const float* __restrict__ u, const float* __restrict__ q,
                 float* __restrict__ out) {
    extern __shared__ char smem[];
    __shared__ alignas(8)  uint64_t mbars[NBUF];
    __shared__ alignas(16) float s_consts[B][8];
    __shared__ float warp_sums[16];
    __shared__ bool  is_last;

    const int tid  = threadIdx.x;
    const int bidx = blockIdx.x;
    const uint32_t s0  = (uint32_t)__cvta_generic_to_shared(smem);
    const uint32_t mbb = (uint32_t)__cvta_generic_to_shared(&mbars[0]);

    const int npairs = (NPAIR - 1 - bidx) / GRID + 1;   // 14 or 13

    if (tid == 0) {
        #pragma unroll
        for (int i = 0; i < NBUF; ++i) mbar_init(mbb + i * 8, 1);
    }
    if (tid < B) {      // per-batch constants, once per CTA
        const float L2_098 = -0.0291463173f;               // log2(0.98)
        int   tb = t[tid];
        float pt = ex2((float)(tb + 1) * L2_098);          // 0.98^(t+1)
        int   tm1 = (tb + TIMESTEPS - 1) % TIMESTEPS;      // Qt[t-1] wraps at t=0
        float pp = ex2((float)(tm1 + 1) * L2_098);
        float flip_t = 0.5f - 0.5f * pt, omt = 0.5f + 0.5f * pt;
        float flip_p = 0.5f - 0.5f * pp, omp = 0.5f + 0.5f * pp;
        float r_omt = rcp(omt), r_flip = rcp(flip_t);
        s_consts[tid][0] = flip_t;
        s_consts[tid][1] = omt;
        s_consts[tid][2] = 0.01f * flip_p * r_omt;   // qt00
        s_consts[tid][3] = 0.99f * flip_p * r_flip;  // qt01
        s_consts[tid][4] = 0.01f * omp    * r_flip;  // qt10
        s_consts[tid][5] = 0.99f * omp    * r_omt;   // qt11
        s_consts[tid][6] = 0.0f;  s_consts[tid][7] = 0.0f;
    }
    __syncthreads();

    // prologue: fill prefetch depth (pairs 0..2)
    if (tid == 0) {
        #pragma unroll
        for (int p = 0; p < NBUF - 1; ++p)
            if (p < npairs)
                produce(mk_geom(bidx + p * GRID), adj, u, q,
                        s0 + (uint32_t)(p * BUFB), mbb + p * 8);
    }

    float s = 0.0f;
    int pid = bidx;
    for (int j = 0; j < npairs; ++j, pid += GRID) {
        if (j) __syncthreads();               // pair j-1 fully consumed before its slot refills
        if (tid == 0 && j + NBUF - 1 < npairs)
            produce(mk_geom(pid + (NBUF - 1) * GRID), adj, u, q,
                    s0 + (uint32_t)(((j + NBUF - 1) & (NBUF - 1)) * BUFB),
                    mbb + ((j + NBUF - 1) & (NBUF - 1)) * 8);
        Geom g = mk_geom(pid);
        const int sl = j & (NBUF - 1);
        mbar_wait(mbb + sl * 8, (uint32_t)((j >> 2) & 1));
        s += compute_pair(g, smem + sl * BUFB, s_consts[g.b], tid);
    }

    // Block reduction (16 warps)
    #pragma unroll
    for (int off = 16; off; off >>= 1) s += __shfl_down_sync(0xffffffffu, s, off);
    const int lane = tid & 31, wid = tid >> 5;
    if (lane == 0) warp_sums[wid] = s;
    __syncthreads();
    if (wid == 0) {
        s = (lane < 16) ? warp_sums[lane] : 0.0f;
        #pragma unroll
        for (int off = 8; off; off >>= 1) s += __shfl_down_sync(0xffffffffu, s, off);
        if (lane == 0) g_partials[bidx] = s;
    }

    // Last-block-standing final reduction (counter wraps to 0 -> replayable)
    __threadfence();
    if (tid == 0) {
        unsigned v = atomicInc(&g_count, GRID - 1);
        is_last = (v == GRID - 1);
    }
    __syncthreads();
    if (is_last) {
        float acc = 0.0f;
        for (int idx = tid; idx < GRID; idx += NTHR) acc += g_partials[idx];
        #pragma unroll
        for (int off = 16; off; off >>= 1) acc += __shfl_down_sync(0xffffffffu, acc, off);
        if (lane == 0) warp_sums[wid] = acc;
        __syncthreads();
        if (wid == 0) {
            acc = (lane < 16) ? warp_sums[lane] : 0.0f;
            #pragma unroll
            for (int off = 8; off; off >>= 1) acc += __shfl_down_sync(0xffffffffu, acc, off);
            if (lane == 0) out[0] = acc * (1.0f / (float)(B * E));
        }
    }
}

extern "C" void kernel_launch(void* const* d_in, const int* in_sizes, int n_in,
                              void* d_out, int out_size) {
    // metadata order: adj_start (int32), t (int32), u (f32), q_approx (f32)
    const int*   adj = (const int*)d_in[0];
    const int*   t   = (const int*)d_in[1];
    const float* u   = (const float*)d_in[2];
    const float* q   = (const float*)d_in[3];
    float* out = (float*)d_out;

    // Function attributes (context-level, capture-legal, no allocation).
    cudaFuncSetAttribute(loss_kernel,
                         cudaFuncAttributeMaxDynamicSharedMemorySize, SMEM_DYN);
    cudaFuncSetAttribute(loss_kernel,
                         cudaFuncAttributePreferredSharedMemoryCarveout,
                         cudaSharedmemCarveoutMaxShared);

    loss_kernel<<<GRID, NTHR, SMEM_DYN>>>(adj, t, u, q, out);
}